// round 5
// baseline (speedup 1.0000x reference)
#include <cuda_runtime.h>
#include <cstdint>

// ModulatedConv2D: B=16, Cin=Cout=512, H=W=32, k=3, pad=1.
// out[b,o] = sigma[b,o] * conv2d( x[b,i]*GAIN*style[b,i], weight )[o]
// sigma[b,o] = rsqrt( GAIN^2 * sum_i style[b,i]^2 * wsq[o,i] + 1e-8 )

#define Bn 16
#define Cn 512
#define On 512
#define Hn 32
#define Wn 32
#define GAINF 0.014731391274719738f  // 1/sqrt(512*9)

__device__ float g_wsq[On * Cn];     // sum over 3x3 of weight^2
__device__ float g_sigma[Bn * On];   // demodulation factors

// ---------------------------------------------------------------------------
// Kernel 1: wsq[o,i] = sum_kk weight[o,i,kh,kw]^2
// ---------------------------------------------------------------------------
__global__ void wsq_kernel(const float* __restrict__ wt) {
    int idx = blockIdx.x * blockDim.x + threadIdx.x;  // o*Cn + i
    if (idx < On * Cn) {
        const float* p = wt + idx * 9;
        float s = 0.f;
#pragma unroll
        for (int k = 0; k < 9; k++) { float v = p[k]; s += v * v; }
        g_wsq[idx] = s;
    }
}

// ---------------------------------------------------------------------------
// Kernel 2: sigma[b,o] = rsqrt(GAIN^2 * sum_i style^2 * wsq + eps)
// grid (O, B), 256 threads
// ---------------------------------------------------------------------------
__global__ void sigma_kernel(const float* __restrict__ style) {
    int o = blockIdx.x;
    int b = blockIdx.y;
    int t = threadIdx.x;
    float s = 0.f;
    for (int i = t; i < Cn; i += 256) {
        float st = style[b * Cn + i];
        s += st * st * g_wsq[o * Cn + i];
    }
    __shared__ float red[8];
#pragma unroll
    for (int off = 16; off; off >>= 1) s += __shfl_xor_sync(0xffffffffu, s, off);
    if ((t & 31) == 0) red[t >> 5] = s;
    __syncthreads();
    if (t < 8) {
        s = red[t];
#pragma unroll
        for (int off = 4; off; off >>= 1) s += __shfl_xor_sync(0xffu, s, off);
        if (t == 0) g_sigma[b * On + o] = rsqrtf(GAINF * GAINF * s + 1e-8f);
    }
}

// ---------------------------------------------------------------------------
// Kernel 3: direct conv, shared weight across batch, style folded into x load,
// sigma folded into epilogue. FFMA2 (fma.rn.f32x2) inner loop.
//
// Block: 256 threads = 8 o-groups (so) x 32 columns (sp).
// Block tile: (b, 64 output channels, 8 rows x 32 cols).
// Each thread: 8 o (so*8..so*8+7 as 4 f32x2 pairs) x 8 rows -> 64 accumulators.
// K loop: input channels in chunks of 8.
// ---------------------------------------------------------------------------
__global__ void __launch_bounds__(256)
conv_kernel(const float* __restrict__ x, const float* __restrict__ style,
            const float* __restrict__ wt, float* __restrict__ out) {
    // sW[(i*9+k)*66 + o]  : stride 66 -> f32x2 pairs 8B-aligned, conflict-padded
    __shared__ __align__(16) float sW[72 * 66];   // 4752 floats
    // sX[i*340 + ry*34 + cx] : 10 halo rows x 34 halo cols per channel
    __shared__ __align__(16) float sX[8 * 340];   // 2720 floats

    const int b   = blockIdx.z;
    const int og0 = blockIdx.y * 64;
    const int y0  = blockIdx.x * 8;
    const int tid = threadIdx.x;
    const int so  = tid >> 5;   // 0..7  (o group)
    const int sp  = tid & 31;   // 0..31 (output column)

    unsigned long long acc[8][4];
#pragma unroll
    for (int v = 0; v < 8; v++)
#pragma unroll
        for (int u = 0; u < 4; u++) acc[v][u] = 0ULL;

    for (int ic0 = 0; ic0 < Cn; ic0 += 8) {
        __syncthreads();
        // --- stage weights: 64 o x 8 i x 9 taps = 4608 elems, coalesced reads ---
#pragma unroll
        for (int l = 0; l < 18; l++) {
            int idx = tid + l * 256;           // 18*256 = 4608
            int o = idx / 72;                  // 72 = 8i*9k contiguous per o
            int r = idx % 72;                  // r = i*9 + k
            sW[r * 66 + o] = wt[(og0 + o) * (Cn * 9) + ic0 * 9 + r];
        }
        // --- stage x halo tiles, folding in GAIN*style[b,i] ---
#pragma unroll
        for (int l = 0; l < 11; l++) {
            int idx = tid + l * 256;
            if (idx < 2720) {
                int i  = idx / 340;
                int r  = idx % 340;
                int ry = r / 34;
                int cx = r % 34;
                int gy = y0 + ry - 1;
                int gx = cx - 1;
                float v = 0.f;
                if ((unsigned)gy < 32u && (unsigned)gx < 32u) {
                    float sg = style[b * Cn + ic0 + i] * GAINF;
                    v = x[((b * Cn + ic0 + i) * Hn + gy) * Wn + gx] * sg;
                }
                sX[idx] = v;
            }
        }
        __syncthreads();

        // --- compute: 8 i x 9 taps, FFMA2 over o-pairs ---
#pragma unroll
        for (int i = 0; i < 8; i++) {
#pragma unroll
            for (int k = 0; k < 9; k++) {
                const int ky = k / 3, kx = k % 3;
                const float* wp = &sW[(i * 9 + k) * 66 + so * 8];
                unsigned long long w0 = *(const unsigned long long*)(wp + 0);
                unsigned long long w1 = *(const unsigned long long*)(wp + 2);
                unsigned long long w2 = *(const unsigned long long*)(wp + 4);
                unsigned long long w3 = *(const unsigned long long*)(wp + 6);
#pragma unroll
                for (int v = 0; v < 8; v++) {
                    float xv = sX[i * 340 + (v + ky) * 34 + sp + kx];
                    unsigned long long xx;
                    asm("mov.b64 %0, {%1, %1};" : "=l"(xx) : "r"(__float_as_uint(xv)));
                    asm("fma.rn.f32x2 %0, %1, %2, %3;"
                        : "=l"(acc[v][0]) : "l"(w0), "l"(xx), "l"(acc[v][0]));
                    asm("fma.rn.f32x2 %0, %1, %2, %3;"
                        : "=l"(acc[v][1]) : "l"(w1), "l"(xx), "l"(acc[v][1]));
                    asm("fma.rn.f32x2 %0, %1, %2, %3;"
                        : "=l"(acc[v][2]) : "l"(w2), "l"(xx), "l"(acc[v][2]));
                    asm("fma.rn.f32x2 %0, %1, %2, %3;"
                        : "=l"(acc[v][3]) : "l"(w3), "l"(xx), "l"(acc[v][3]));
                }
            }
        }
    }

    // --- epilogue: demodulate by sigma[b,o] and store ---
#pragma unroll
    for (int u2 = 0; u2 < 4; u2++) {
        int o = og0 + so * 8 + u2 * 2;
        float s0 = g_sigma[b * On + o];
        float s1 = g_sigma[b * On + o + 1];
#pragma unroll
        for (int v = 0; v < 8; v++) {
            unsigned lo, hi;
            asm("mov.b64 {%0, %1}, %2;" : "=r"(lo), "=r"(hi) : "l"(acc[v][u2]));
            out[((b * On + o    ) * Hn + y0 + v) * Wn + sp] = __uint_as_float(lo) * s0;
            out[((b * On + o + 1) * Hn + y0 + v) * Wn + sp] = __uint_as_float(hi) * s1;
        }
    }
}

// ---------------------------------------------------------------------------
extern "C" void kernel_launch(void* const* d_in, const int* in_sizes, int n_in,
                              void* d_out, int out_size) {
    const float* x     = (const float*)d_in[0];  // [16,512,32,32]
    const float* style = (const float*)d_in[1];  // [16,512]
    const float* wt    = (const float*)d_in[2];  // [512,512,3,3]
    float* out = (float*)d_out;                  // [16,512,32,32]

    wsq_kernel<<<(On * Cn + 255) / 256, 256>>>(wt);
    sigma_kernel<<<dim3(On, Bn), 256>>>(style);
    conv_kernel<<<dim3(Hn / 8, On / 64, Bn), 256>>>(x, style, wt, out);
}

// round 13
// speedup vs baseline: 1.9999x; 1.9999x over previous
#include <cuda_runtime.h>
#include <cstdint>

// ModulatedConv2D: B=16, Cin=Cout=512, H=W=32, k=3, pad=1.
// out[b,o] = sigma[b,o] * conv2d( x[b,i]*style[b,i], weight*GAIN )[o]
// Implicit GEMM via warp-level mma.sync m16n8k8 tf32 (plain sm_103 ISA —
// tcgen05 is unreachable: harness compiles through compute_103, not 103a).

#define Bn 16
#define Cn 512
#define On 512
#define GAINF 0.014731391274719738f  // 1/sqrt(512*9)

__device__ float g_wsq[On * Cn];
__device__ float g_sigma[Bn * On];
// A fragments: [tap(9)][otile16(32)][kstep8(64)][lane(32)][4 regs], tf32 bits
__device__ uint32_t g_wA[9 * 32 * 64 * 32 * 4];

// ---------------------------------------------------------------------------
// Prologue 1a: wsq[o,i] = sum_kk weight^2
// ---------------------------------------------------------------------------
__global__ void wsq_kernel(const float* __restrict__ wt) {
    int idx = blockIdx.x * 256 + threadIdx.x;
    if (idx < On * Cn) {
        const float* p = wt + idx * 9;
        float s = 0.f;
#pragma unroll
        for (int k = 0; k < 9; ++k) { float v = p[k]; s += v * v; }
        g_wsq[idx] = s;
    }
}

// ---------------------------------------------------------------------------
// Prologue 1b: pack weights into mma fragment order (GAIN folded, tf32)
// m16n8k8 A layout: a0=(gid,tg) a1=(gid+8,tg) a2=(gid,tg+4) a3=(gid+8,tg+4)
// ---------------------------------------------------------------------------
__global__ void wfrag_kernel(const float* __restrict__ wt) {
    int id = blockIdx.x * 256 + threadIdx.x;   // over 9*32*64*32 fragment-lanes
    if (id >= 9 * 32 * 64 * 32) return;
    int lane = id & 31;
    int ksg  = (id >> 5) & 63;
    int otg  = (id >> 11) & 31;
    int tap  = id >> 16;
    int gid = lane >> 2, tg = lane & 3;
    int o = otg * 16 + gid;
    int k = ksg * 8 + tg;
    float f0 = wt[((o    ) * Cn + k    ) * 9 + tap] * GAINF;
    float f1 = wt[((o + 8) * Cn + k    ) * 9 + tap] * GAINF;
    float f2 = wt[((o    ) * Cn + k + 4) * 9 + tap] * GAINF;
    float f3 = wt[((o + 8) * Cn + k + 4) * 9 + tap] * GAINF;
    uint32_t u0, u1, u2, u3;
    asm("cvt.rna.tf32.f32 %0, %1;" : "=r"(u0) : "f"(f0));
    asm("cvt.rna.tf32.f32 %0, %1;" : "=r"(u1) : "f"(f1));
    asm("cvt.rna.tf32.f32 %0, %1;" : "=r"(u2) : "f"(f2));
    asm("cvt.rna.tf32.f32 %0, %1;" : "=r"(u3) : "f"(f3));
    ((uint4*)g_wA)[id] = make_uint4(u0, u1, u2, u3);
}

// ---------------------------------------------------------------------------
// Prologue 2: sigma[b,o] = rsqrt(GAIN^2 * sum_i style^2 * wsq + eps)
// ---------------------------------------------------------------------------
__global__ void sigma_kernel(const float* __restrict__ style) {
    int o = blockIdx.x, b = blockIdx.y, t = threadIdx.x;
    float s = 0.f;
    for (int i = t; i < Cn; i += 256) {
        float st = style[b * Cn + i];
        s += st * st * g_wsq[o * Cn + i];
    }
    __shared__ float red[8];
#pragma unroll
    for (int off = 16; off; off >>= 1) s += __shfl_xor_sync(0xffffffffu, s, off);
    if ((t & 31) == 0) red[t >> 5] = s;
    __syncthreads();
    if (t < 8) {
        s = red[t];
#pragma unroll
        for (int off = 4; off; off >>= 1) s += __shfl_xor_sync(0xffu, s, off);
        if (t == 0) g_sigma[b * On + o] = rsqrtf(GAINF * GAINF * s + 1e-8f);
    }
}

// ---------------------------------------------------------------------------
// Main conv. Grid (8 row-tiles, 4 o-tiles, 16 b), 128 threads (4 warps 2x2).
// CTA tile: 128 o x 128 spatial (4 rows x 32 cols). Warp tile 64x64.
// K = 512 channels x 9 taps; channels chunked by 32, taps inner.
// B fragments straight from halo smem (stride 232: conflict-free).
// A fragments via LDG.128 from pre-packed g_wA (L1/L2-hot).
// ---------------------------------------------------------------------------
#define XH_STRIDE 232

#define MMA_TF32(c, a, bb0, bb1)                                              \
    asm("mma.sync.aligned.m16n8k8.row.col.f32.tf32.tf32.f32 "                 \
        "{%0,%1,%2,%3}, {%4,%5,%6,%7}, {%8,%9}, {%0,%1,%2,%3};"               \
        : "+f"((c)[0]), "+f"((c)[1]), "+f"((c)[2]), "+f"((c)[3])              \
        : "r"((a).x), "r"((a).y), "r"((a).z), "r"((a).w), "r"(bb0), "r"(bb1))

__global__ void __launch_bounds__(128, 2)
conv_mma_kernel(const float* __restrict__ x, const float* __restrict__ style,
                float* __restrict__ out) {
    __shared__ float sXH[32 * XH_STRIDE];   // 32ch x (6 rows x 34 cols halo)

    const int b   = blockIdx.z;
    const int oty = blockIdx.y;          // o-tile: 128 channels
    const int y0  = blockIdx.x * 4;      // 4 output rows
    const int tid = threadIdx.x;
    const int wid = tid >> 5, lane = tid & 31;
    const int warp_m = wid >> 1, warp_n = wid & 1;
    const int gid = lane >> 2, tg = lane & 3;

    float acc[4][8][4];
#pragma unroll
    for (int mt = 0; mt < 4; ++mt)
#pragma unroll
        for (int nt = 0; nt < 8; ++nt)
#pragma unroll
            for (int c = 0; c < 4; ++c) acc[mt][nt][c] = 0.f;

    // per-thread halo offsets for B fragments (col n = ntbase + gid)
    int hoff[8];
#pragma unroll
    for (int nt = 0; nt < 8; ++nt) {
        int n = warp_n * 64 + nt * 8 + gid;
        hoff[nt] = (n >> 5) * 34 + (n & 31);
    }

    const int bC = b * Cn;

#pragma unroll 1
    for (int ic0 = 0; ic0 < Cn; ic0 += 32) {
        __syncthreads();   // previous chunk's B reads done
        // ---- stage halo: 32ch x 6 x 34, style-modulated, tf32-rounded ----
#pragma unroll 1
        for (int j = 0; j < 51; ++j) {
            int idx = j * 128 + tid;
            if (idx < 6528) {
                int i   = idx / 204;
                int rem = idx - i * 204;
                int r   = rem / 34;
                int c   = rem - r * 34;
                int gy = y0 + r - 1, gx = c - 1;
                float v = 0.f;
                if ((unsigned)gy < 32u && (unsigned)gx < 32u)
                    v = x[((bC + ic0 + i) * 32 + gy) * 32 + gx] * style[bC + ic0 + i];
                uint32_t u;
                asm("cvt.rna.tf32.f32 %0, %1;" : "=r"(u) : "f"(v));
                sXH[i * XH_STRIDE + r * 34 + c] = __uint_as_float(u);
            }
        }
        __syncthreads();

#pragma unroll 1
        for (int tap = 0; tap < 9; ++tap) {
            const int dy = tap / 3, dx = tap - dy * 3;
            const int dd = dy * 34 + dx;
            const uint4* Abase = (const uint4*)g_wA +
                ((tap * 32 + (oty * 8 + warp_m * 4)) * 64 + (ic0 >> 3)) * 32 + lane;
#pragma unroll
            for (int ks = 0; ks < 4; ++ks) {
                const float* pB = sXH + (ks * 8 + tg) * XH_STRIDE + dd;
                uint32_t b0[8], b1[8];
#pragma unroll
                for (int nt = 0; nt < 8; ++nt) {
                    b0[nt] = __float_as_uint(pB[hoff[nt]]);
                    b1[nt] = __float_as_uint(pB[hoff[nt] + 4 * XH_STRIDE]);
                }
                uint4 A[4];
#pragma unroll
                for (int mt = 0; mt < 4; ++mt)
                    A[mt] = __ldg(Abase + mt * (64 * 32) + ks * 32);
#pragma unroll
                for (int mt = 0; mt < 4; ++mt)
#pragma unroll
                    for (int nt = 0; nt < 8; ++nt)
                        MMA_TF32(acc[mt][nt], A[mt], b0[nt], b1[nt]);
            }
        }
    }

    // ---- epilogue: demodulate, direct float2 stores ----
    // C layout: c0=(gid, 2tg) c1=(gid, 2tg+1) c2=(gid+8, 2tg) c3=(gid+8, 2tg+1)
    const int og0 = oty * 128 + warp_m * 64;
#pragma unroll
    for (int mt = 0; mt < 4; ++mt) {
        int o0 = og0 + mt * 16 + gid;
        float s0 = g_sigma[b * On + o0];
        float s1 = g_sigma[b * On + o0 + 8];
        float* r0 = out + (size_t)(b * On + o0) * 1024;
        float* r1 = out + (size_t)(b * On + o0 + 8) * 1024;
#pragma unroll
        for (int nt = 0; nt < 8; ++nt) {
            int n = warp_n * 64 + nt * 8 + 2 * tg;
            int off = (y0 + (n >> 5)) * 32 + (n & 31);
            float2 v0 = make_float2(acc[mt][nt][0] * s0, acc[mt][nt][1] * s0);
            float2 v1 = make_float2(acc[mt][nt][2] * s1, acc[mt][nt][3] * s1);
            *(float2*)(r0 + off) = v0;
            *(float2*)(r1 + off) = v1;
        }
    }
}

// ---------------------------------------------------------------------------
extern "C" void kernel_launch(void* const* d_in, const int* in_sizes, int n_in,
                              void* d_out, int out_size) {
    const float* x     = (const float*)d_in[0];  // [16,512,32,32]
    const float* style = (const float*)d_in[1];  // [16,512]
    const float* wt    = (const float*)d_in[2];  // [512,512,3,3]
    float* out = (float*)d_out;

    wsq_kernel<<<(On * Cn + 255) / 256, 256>>>(wt);
    wfrag_kernel<<<(9 * 32 * 64 * 32 + 255) / 256, 256>>>(wt);
    sigma_kernel<<<dim3(On, Bn), 256>>>(style);
    conv_mma_kernel<<<dim3(8, 4, Bn), 128>>>(x, style, out);
}

// round 14
// speedup vs baseline: 2.8064x; 1.4033x over previous
#include <cuda_runtime.h>
#include <cstdint>

// ModulatedConv2D: B=16, Cin=Cout=512, H=W=32, k=3, pad=1.
// out[b,o] = sigma[b,o] * conv2d( x[b,i]*style[b,i], weight*GAIN )[o]
// Implicit GEMM via warp-level mma.sync m16n8k8 tf32 (plain sm_103 ISA).
// R14: 256-thr CTA, 8 warps, 64x32 warp tile -> ~110 regs, 2x warps/SMSP.

#define Bn 16
#define Cn 512
#define On 512
#define GAINF 0.014731391274719738f  // 1/sqrt(512*9)

__device__ float g_wsq[On * Cn];
__device__ float g_sigma[Bn * On];
// A fragments: [tap(9)][otile16(32)][kstep8(64)][lane(32)][4 regs], tf32 bits
__device__ uint32_t g_wA[9 * 32 * 64 * 32 * 4];

// ---------------------------------------------------------------------------
// Prologue 1a: wsq[o,i] = sum_kk weight^2
// ---------------------------------------------------------------------------
__global__ void wsq_kernel(const float* __restrict__ wt) {
    int idx = blockIdx.x * 256 + threadIdx.x;
    if (idx < On * Cn) {
        const float* p = wt + idx * 9;
        float s = 0.f;
#pragma unroll
        for (int k = 0; k < 9; ++k) { float v = p[k]; s += v * v; }
        g_wsq[idx] = s;
    }
}

// ---------------------------------------------------------------------------
// Prologue 1b: pack weights into mma fragment order (GAIN folded, tf32)
// m16n8k8 A layout: a0=(gid,tg) a1=(gid+8,tg) a2=(gid,tg+4) a3=(gid+8,tg+4)
// ---------------------------------------------------------------------------
__global__ void wfrag_kernel(const float* __restrict__ wt) {
    int id = blockIdx.x * 256 + threadIdx.x;   // over 9*32*64*32 fragment-lanes
    if (id >= 9 * 32 * 64 * 32) return;
    int lane = id & 31;
    int ksg  = (id >> 5) & 63;
    int otg  = (id >> 11) & 31;
    int tap  = id >> 16;
    int gid = lane >> 2, tg = lane & 3;
    int o = otg * 16 + gid;
    int k = ksg * 8 + tg;
    float f0 = wt[((o    ) * Cn + k    ) * 9 + tap] * GAINF;
    float f1 = wt[((o + 8) * Cn + k    ) * 9 + tap] * GAINF;
    float f2 = wt[((o    ) * Cn + k + 4) * 9 + tap] * GAINF;
    float f3 = wt[((o + 8) * Cn + k + 4) * 9 + tap] * GAINF;
    uint32_t u0, u1, u2, u3;
    asm("cvt.rna.tf32.f32 %0, %1;" : "=r"(u0) : "f"(f0));
    asm("cvt.rna.tf32.f32 %0, %1;" : "=r"(u1) : "f"(f1));
    asm("cvt.rna.tf32.f32 %0, %1;" : "=r"(u2) : "f"(f2));
    asm("cvt.rna.tf32.f32 %0, %1;" : "=r"(u3) : "f"(f3));
    ((uint4*)g_wA)[id] = make_uint4(u0, u1, u2, u3);
}

// ---------------------------------------------------------------------------
// Prologue 2: sigma[b,o] = rsqrt(GAIN^2 * sum_i style^2 * wsq + eps)
// ---------------------------------------------------------------------------
__global__ void sigma_kernel(const float* __restrict__ style) {
    int o = blockIdx.x, b = blockIdx.y, t = threadIdx.x;
    float s = 0.f;
    for (int i = t; i < Cn; i += 256) {
        float st = style[b * Cn + i];
        s += st * st * g_wsq[o * Cn + i];
    }
    __shared__ float red[8];
#pragma unroll
    for (int off = 16; off; off >>= 1) s += __shfl_xor_sync(0xffffffffu, s, off);
    if ((t & 31) == 0) red[t >> 5] = s;
    __syncthreads();
    if (t < 8) {
        s = red[t];
#pragma unroll
        for (int off = 4; off; off >>= 1) s += __shfl_xor_sync(0xffu, s, off);
        if (t == 0) g_sigma[b * On + o] = rsqrtf(GAINF * GAINF * s + 1e-8f);
    }
}

// ---------------------------------------------------------------------------
// Main conv. Grid (8 row-tiles, 4 o-tiles, 16 b), 256 threads = 8 warps (2x4).
// CTA tile: 128 o x 128 spatial (4 rows x 32 cols). Warp tile 64 o x 32 n.
// K = 512 channels x 9 taps; channels chunked by 32, taps inner.
// B fragments straight from halo smem (stride 232: conflict-free).
// A fragments via LDG.128 from pre-packed g_wA (L1/L2-hot).
// ---------------------------------------------------------------------------
#define XH_STRIDE 232

#define MMA_TF32(c, a, bb0, bb1)                                              \
    asm("mma.sync.aligned.m16n8k8.row.col.f32.tf32.tf32.f32 "                 \
        "{%0,%1,%2,%3}, {%4,%5,%6,%7}, {%8,%9}, {%0,%1,%2,%3};"               \
        : "+f"((c)[0]), "+f"((c)[1]), "+f"((c)[2]), "+f"((c)[3])              \
        : "r"((a).x), "r"((a).y), "r"((a).z), "r"((a).w), "r"(bb0), "r"(bb1))

__global__ void __launch_bounds__(256, 2)
conv_mma_kernel(const float* __restrict__ x, const float* __restrict__ style,
                float* __restrict__ out) {
    __shared__ float sXH[32 * XH_STRIDE];   // 32ch x (6 rows x 34 cols halo)

    const int b   = blockIdx.z;
    const int oty = blockIdx.y;          // o-tile: 128 channels
    const int y0  = blockIdx.x * 4;      // 4 output rows
    const int tid = threadIdx.x;
    const int wid = tid >> 5, lane = tid & 31;
    const int warp_m = wid >> 2;         // 0..1 : 64 o-channels each
    const int warp_n = wid & 3;          // 0..3 : 32 spatial cols each
    const int gid = lane >> 2, tg = lane & 3;

    float acc[4][4][4];
#pragma unroll
    for (int mt = 0; mt < 4; ++mt)
#pragma unroll
        for (int nt = 0; nt < 4; ++nt)
#pragma unroll
            for (int c = 0; c < 4; ++c) acc[mt][nt][c] = 0.f;

    // per-thread halo offsets for B fragments (col n = warp_n*32 + nt*8 + gid)
    int hoff[4];
#pragma unroll
    for (int nt = 0; nt < 4; ++nt) {
        int n = warp_n * 32 + nt * 8 + gid;
        hoff[nt] = (n >> 5) * 34 + (n & 31);
    }

    const int bC = b * Cn;

#pragma unroll 1
    for (int ic0 = 0; ic0 < Cn; ic0 += 32) {
        __syncthreads();   // previous chunk's B reads done
        // ---- stage halo: 32ch x 6 x 34, style-modulated, tf32-rounded ----
#pragma unroll 1
        for (int j = 0; j < 26; ++j) {
            int idx = j * 256 + tid;
            if (idx < 6528) {
                int i   = idx / 204;
                int rem = idx - i * 204;
                int r   = rem / 34;
                int c   = rem - r * 34;
                int gy = y0 + r - 1, gx = c - 1;
                float v = 0.f;
                if ((unsigned)gy < 32u && (unsigned)gx < 32u)
                    v = x[((bC + ic0 + i) * 32 + gy) * 32 + gx] * style[bC + ic0 + i];
                uint32_t u;
                asm("cvt.rna.tf32.f32 %0, %1;" : "=r"(u) : "f"(v));
                sXH[i * XH_STRIDE + r * 34 + c] = __uint_as_float(u);
            }
        }
        __syncthreads();

#pragma unroll 1
        for (int tap = 0; tap < 9; ++tap) {
            const int dy = tap / 3, dx = tap - dy * 3;
            const int dd = dy * 34 + dx;
            const uint4* Abase = (const uint4*)g_wA +
                ((tap * 32 + (oty * 8 + warp_m * 4)) * 64 + (ic0 >> 3)) * 32 + lane;
#pragma unroll
            for (int ks = 0; ks < 4; ++ks) {
                // A fragments first (long-latency LDG issues early)
                uint4 A[4];
#pragma unroll
                for (int mt = 0; mt < 4; ++mt)
                    A[mt] = __ldg(Abase + mt * (64 * 32) + ks * 32);
                const float* pB = sXH + (ks * 8 + tg) * XH_STRIDE + dd;
                uint32_t b0[4], b1[4];
#pragma unroll
                for (int nt = 0; nt < 4; ++nt) {
                    b0[nt] = __float_as_uint(pB[hoff[nt]]);
                    b1[nt] = __float_as_uint(pB[hoff[nt] + 4 * XH_STRIDE]);
                }
#pragma unroll
                for (int mt = 0; mt < 4; ++mt)
#pragma unroll
                    for (int nt = 0; nt < 4; ++nt)
                        MMA_TF32(acc[mt][nt], A[mt], b0[nt], b1[nt]);
            }
        }
    }

    // ---- epilogue: demodulate, direct float2 stores ----
    // C layout: c0=(gid, 2tg) c1=(gid, 2tg+1) c2=(gid+8, 2tg) c3=(gid+8, 2tg+1)
    const int og0 = oty * 128 + warp_m * 64;
#pragma unroll
    for (int mt = 0; mt < 4; ++mt) {
        int o0 = og0 + mt * 16 + gid;
        float s0 = g_sigma[b * On + o0];
        float s1 = g_sigma[b * On + o0 + 8];
        float* r0 = out + (size_t)(b * On + o0) * 1024;
        float* r1 = out + (size_t)(b * On + o0 + 8) * 1024;
#pragma unroll
        for (int nt = 0; nt < 4; ++nt) {
            int n = warp_n * 32 + nt * 8 + 2 * tg;
            int off = (y0 + (n >> 5)) * 32 + (n & 31);
            float2 v0 = make_float2(acc[mt][nt][0] * s0, acc[mt][nt][1] * s0);
            float2 v1 = make_float2(acc[mt][nt][2] * s1, acc[mt][nt][3] * s1);
            *(float2*)(r0 + off) = v0;
            *(float2*)(r1 + off) = v1;
        }
    }
}

// ---------------------------------------------------------------------------
extern "C" void kernel_launch(void* const* d_in, const int* in_sizes, int n_in,
                              void* d_out, int out_size) {
    const float* x     = (const float*)d_in[0];  // [16,512,32,32]
    const float* style = (const float*)d_in[1];  // [16,512]
    const float* wt    = (const float*)d_in[2];  // [512,512,3,3]
    float* out = (float*)d_out;

    wsq_kernel<<<(On * Cn + 255) / 256, 256>>>(wt);
    wfrag_kernel<<<(9 * 32 * 64 * 32 + 255) / 256, 256>>>(wt);
    sigma_kernel<<<dim3(On, Bn), 256>>>(style);
    conv_mma_kernel<<<dim3(8, 4, Bn), 256>>>(x, style, out);
}